// round 15
// baseline (speedup 1.0000x reference)
#include <cuda_runtime.h>
#include <cuda_fp16.h>
#include <math.h>

#define NUM_CLASSES 200
#define NUM_PROTO   10
#define EMBED_D     512
#define NQ          8192
#define MC          96      // S/sv/idx capacity
#define TCAP        64      // fp16 rows staged in smem
#define EPSILON_    0.01f
#define ITERS       5
#define MOM         0.02f
#define NT          512
#define ROWB        1040    // bytes per staged fp16 row (520 halves, bank-staggered)
#define PIK         104     // pi_h K padding (208B row stride: conflict-free ldmatrix)

// dynamic smem layout (bytes), all 16B aligned
#define OFFB_TOKH   0                       // 64 * 1040 = 66560
#define OFFB_PROTOH 66560                   // 16 * 1040 = 16640
#define OFFB_S      83200                   // 10*96*4 = 3840
#define OFFB_SV     87040                   // 96*4
#define OFFB_INVN   87424                   // 96*4
#define OFFB_IDX    87808                   // 96*4
#define OFFB_PIH    88192                   // 16 * 208 = 3328 fp16 pi
#define SMEM_BYTES  91520

extern __shared__ char smc[];

__device__ __forceinline__ void ldm_x4(unsigned addr, unsigned &a0, unsigned &a1,
                                       unsigned &a2, unsigned &a3) {
    asm volatile("ldmatrix.sync.aligned.m8n8.x4.shared.b16 {%0,%1,%2,%3}, [%4];"
        : "=r"(a0), "=r"(a1), "=r"(a2), "=r"(a3) : "r"(addr));
}
__device__ __forceinline__ void ldm_x2(unsigned addr, unsigned &b0, unsigned &b1) {
    asm volatile("ldmatrix.sync.aligned.m8n8.x2.shared.b16 {%0,%1}, [%2];"
        : "=r"(b0), "=r"(b1) : "r"(addr));
}
__device__ __forceinline__ void ldm_x2t(unsigned addr, unsigned &b0, unsigned &b1) {
    asm volatile("ldmatrix.sync.aligned.m8n8.x2.trans.shared.b16 {%0,%1}, [%2];"
        : "=r"(b0), "=r"(b1) : "r"(addr));
}
__device__ __forceinline__ void mma16816(float &c0, float &c1, float &c2, float &c3,
                                         unsigned a0, unsigned a1, unsigned a2, unsigned a3,
                                         unsigned b0, unsigned b1) {
    asm volatile("mma.sync.aligned.m16n8k16.row.col.f32.f16.f16.f32 "
        "{%0,%1,%2,%3},{%4,%5,%6,%7},{%8,%9},{%0,%1,%2,%3};"
        : "+f"(c0), "+f"(c1), "+f"(c2), "+f"(c3)
        : "r"(a0), "r"(a1), "r"(a2), "r"(a3), "r"(b0), "r"(b1));
}

__global__ void __launch_bounds__(NT, 2) fused_kernel(
    const float* __restrict__ tokens,
    const void*  __restrict__ labels_v,
    const float* __restrict__ protos_g,
    float* __restrict__ out)
{
    __shared__ float su[NUM_PROTO];
    __shared__ __align__(16) float stage2[256];   // [16 rows][16 warps] partial ss
    __shared__ float su2[16];
    __shared__ int   s_cnt;

    float* sS   = (float*)(smc + OFFB_S);
    float* sv   = (float*)(smc + OFFB_SV);
    float* invn = (float*)(smc + OFFB_INVN);
    int*   idx  = (int*)(smc + OFFB_IDX);

    const int c    = blockIdx.x;
    const int tid  = threadIdx.x;
    const int lane = tid & 31;
    const int wid  = tid >> 5;

    if (tid == 0) s_cnt = 0;
    if (tid < NUM_PROTO) su[tid] = 0.f;
    if (tid < MC)        sv[tid] = 0.f;
    // zero pi_h (rows 10-15 and cols >= m must be 0 for the phase-4 MMA)
    for (int t = tid; t < 16 * PIK / 2; t += NT)
        ((unsigned*)(smc + OFFB_PIH))[t] = 0u;

    // ---- label scan round 1 + dtype detect, one L2 exposure ----
    // First 32KB: int64 buffer -> labels 0..4095 (odd words all zero);
    // int32 buffer -> ALL labels (odd words nonzero somewhere).
    const int4* L = (const int4*)labels_v;
    int4 v[4];
    #pragma unroll
    for (int k = 0; k < 4; k++) v[k] = L[tid + NT * k];
    int nz = v[0].y | v[0].w | v[1].y | v[1].w |
             v[2].y | v[2].w | v[3].y | v[3].w;
    const int is64 = __syncthreads_or(nz != 0) ? 0 : 1;  // barrier orders inits

    if (!is64) {
        #pragma unroll
        for (int k = 0; k < 4; k++) {
            int base = 4 * (tid + NT * k);
            if (v[k].x == c) { int p = atomicAdd(&s_cnt, 1); if (p < MC) idx[p] = base; }
            if (v[k].y == c) { int p = atomicAdd(&s_cnt, 1); if (p < MC) idx[p] = base + 1; }
            if (v[k].z == c) { int p = atomicAdd(&s_cnt, 1); if (p < MC) idx[p] = base + 2; }
            if (v[k].w == c) { int p = atomicAdd(&s_cnt, 1); if (p < MC) idx[p] = base + 3; }
        }
    } else {
        int4 w4[4];
        #pragma unroll
        for (int k = 0; k < 4; k++) w4[k] = L[tid + NT * (k + 4)];
        #pragma unroll
        for (int k = 0; k < 4; k++) {
            int base = 2 * (tid + NT * k);
            if (v[k].x == c) { int p = atomicAdd(&s_cnt, 1); if (p < MC) idx[p] = base; }
            if (v[k].z == c) { int p = atomicAdd(&s_cnt, 1); if (p < MC) idx[p] = base + 1; }
        }
        #pragma unroll
        for (int k = 0; k < 4; k++) {
            int base = 2 * (tid + NT * (k + 4));
            if (w4[k].x == c) { int p = atomicAdd(&s_cnt, 1); if (p < MC) idx[p] = base; }
            if (w4[k].z == c) { int p = atomicAdd(&s_cnt, 1); if (p < MC) idx[p] = base + 1; }
        }
    }

    // ---- proto fp32 -> fp16 smem (overlaps label extraction latency) ----
    {
        const float4* pg = (const float4*)(protos_g + (size_t)c * NUM_PROTO * EMBED_D);
        for (int t = tid; t < NUM_PROTO * EMBED_D / 4; t += NT) {
            float4 vv = pg[t];
            int p = t >> 7, d4 = t & 127;
            __half2* dst = (__half2*)(smc + OFFB_PROTOH + p * ROWB) + d4 * 2;
            dst[0] = __floats2half2_rn(vv.x, vv.y);
            dst[1] = __floats2half2_rn(vv.z, vv.w);
        }
    }
    __syncthreads();
    const int m    = (s_cnt < MC) ? s_cnt : MC;
    const int mcap = (m < TCAP) ? m : TCAP;
    const int ks   = (mcap + 15) >> 4;          // phase-4 k-steps

    // ---- Pre-pass: warp per row: load fp32, normalize, stage fp16 ----
    for (int j = wid; j < m; j += 16) {
        const float4* tk = (const float4*)(tokens + (size_t)idx[j] * EMBED_D);
        float4 r[4];
        float ss = 0.f;
        #pragma unroll
        for (int k = 0; k < 4; k++) {
            r[k] = tk[lane + 32 * k];
            ss += r[k].x*r[k].x + r[k].y*r[k].y + r[k].z*r[k].z + r[k].w*r[k].w;
        }
        #pragma unroll
        for (int o = 16; o; o >>= 1) ss += __shfl_xor_sync(0xffffffffu, ss, o);
        float inv = rsqrtf(ss);
        if (lane == 0) invn[j] = inv;
        if (j < TCAP) {
            __half2* row = (__half2*)(smc + OFFB_TOKH + j * ROWB);
            #pragma unroll
            for (int k = 0; k < 4; k++) {
                int h2 = (lane + 32 * k) * 2;
                row[h2]     = __floats2half2_rn(r[k].x * inv, r[k].y * inv);
                row[h2 + 1] = __floats2half2_rn(r[k].z * inv, r[k].w * inv);
            }
        }
    }
    // zero tok_h rows [mcap, 16*ks) — read by phase-4 MMA, never staged
    for (int t = tid; t < (16 * ks - mcap) * 260; t += NT) {
        int r = mcap + t / 260, q = t % 260;
        *((unsigned*)(smc + OFFB_TOKH + r * ROWB) + q) = 0u;
    }
    __syncthreads();

    // ---- Phase 2: S = proto @ tok_norm^T via tensor cores ----
    if (wid < 8) {
        const int jt = wid * 8;
        const int g  = lane >> 3;
        const int r8 = lane & 7;
        unsigned a_base = (unsigned)__cvta_generic_to_shared(
            smc + OFFB_PROTOH + ((g & 1) * 8 + r8) * ROWB + (g >> 1) * 16);
        unsigned b_base = (unsigned)__cvta_generic_to_shared(
            smc + OFFB_TOKH + (jt + r8) * ROWB + (g & 1) * 16);
        float c0 = 0.f, c1 = 0.f, c2 = 0.f, c3 = 0.f;
        #pragma unroll 8
        for (int kk = 0; kk < 32; kk++) {
            unsigned a0, a1, a2, a3, b0, b1;
            ldm_x4(a_base + kk * 32, a0, a1, a2, a3);
            ldm_x2(b_base + kk * 32, b0, b1);
            mma16816(c0, c1, c2, c3, a0, a1, a2, a3, b0, b1);
        }
        const int row = lane >> 2;
        const int j0  = jt + 2 * (lane & 3);
        sS[row * MC + j0]     = c0;
        sS[row * MC + j0 + 1] = c1;
        if (row + 8 < NUM_PROTO) {
            sS[(row + 8) * MC + j0]     = c2;
            sS[(row + 8) * MC + j0 + 1] = c3;
        }
    } else if (m > TCAP) {
        // rare fallback: rows 64..m-1 from raw fp32 global -> needs invn
        for (int j = TCAP + (wid - 8); j < m; j += 8) {
            const float4* tk = (const float4*)(tokens + (size_t)idx[j] * EMBED_D + 16 * lane);
            float4 t[4];
            #pragma unroll
            for (int k = 0; k < 4; k++) t[k] = tk[k];
            float iv = invn[j];
            #pragma unroll
            for (int p = 0; p < NUM_PROTO; p++) {
                const __half2* ph = (const __half2*)(smc + OFFB_PROTOH + p * ROWB) + lane * 8;
                float d = 0.f;
                #pragma unroll
                for (int k = 0; k < 4; k++) {
                    float2 f0 = __half22float2(ph[2 * k]);
                    float2 f1 = __half22float2(ph[2 * k + 1]);
                    d += f0.x * t[k].x + f0.y * t[k].y + f1.x * t[k].z + f1.y * t[k].w;
                }
                #pragma unroll
                for (int o = 16; o; o >>= 1) d += __shfl_xor_sync(0xffffffffu, d, o);
                if (lane == 0) sS[p * MC + j] = d * iv;
            }
        }
    }
    __syncthreads();

    // ---- Phase 3: Sinkhorn (warps 0-9; named barrier 1, 320 threads) ----
    if (m > 0 && wid < NUM_PROTO) {
        const float log_a = __logf(1.0f / (float)NUM_PROTO + 1e-8f);
        const float log_b = __logf(1.0f / (float)m + 1e-8f);
        const float inv_eps = 1.0f / EPSILON_;
        const int p = wid;

        const float s0 = (lane      < m) ? sS[p * MC + lane]      : -INFINITY;
        const float s1 = (lane + 32 < m) ? sS[p * MC + lane + 32] : -INFINITY;
        const float s2 = (lane + 64 < m) ? sS[p * MC + lane + 64] : -INFINITY;
        float scol[NUM_PROTO];
        if (tid < m) {
            #pragma unroll
            for (int pp = 0; pp < NUM_PROTO; pp++) scol[pp] = sS[pp * MC + tid];
        }

        for (int it = 0; it < ITERS; it++) {
            {
                float up = su[p];
                float t0 = (s0 + up + sv[lane])      * inv_eps;
                float t1 = (s1 + up + sv[lane + 32]) * inv_eps;
                float t2 = (s2 + up + sv[lane + 64]) * inv_eps;
                float mx = fmaxf(t0, fmaxf(t1, t2));
                #pragma unroll
                for (int o = 16; o; o >>= 1)
                    mx = fmaxf(mx, __shfl_xor_sync(0xffffffffu, mx, o));
                float sum = __expf(t0 - mx) + __expf(t1 - mx) + __expf(t2 - mx);
                #pragma unroll
                for (int o = 16; o; o >>= 1)
                    sum += __shfl_xor_sync(0xffffffffu, sum, o);
                if (lane == 0)
                    su[p] = EPSILON_ * (log_a - (mx + __logf(sum))) + up;
            }
            asm volatile("bar.sync 1, 320;" ::: "memory");
            if (tid < m) {
                float vj = sv[tid];
                float mx = -INFINITY;
                #pragma unroll
                for (int pp = 0; pp < NUM_PROTO; pp++)
                    mx = fmaxf(mx, (scol[pp] + su[pp] + vj) * inv_eps);
                float sum = 0.f;
                #pragma unroll
                for (int pp = 0; pp < NUM_PROTO; pp++)
                    sum += __expf((scol[pp] + su[pp] + vj) * inv_eps - mx);
                sv[tid] = EPSILON_ * (log_b - (mx + __logf(sum))) + vj;
            }
            asm volatile("bar.sync 1, 320;" ::: "memory");
        }

        if (tid < m) {   // pi, column-normalized; fp32 to sS (tail) + fp16 to pi_h (MMA)
            float vj = sv[tid];
            float col[NUM_PROTO];
            float cs = 0.f;
            #pragma unroll
            for (int pp = 0; pp < NUM_PROTO; pp++) {
                col[pp] = __expf((scol[pp] + su[pp] + vj) * inv_eps);
                cs += col[pp];
            }
            float inv = 1.0f / cs;
            __half* ph = (__half*)(smc + OFFB_PIH);
            #pragma unroll
            for (int pp = 0; pp < NUM_PROTO; pp++) {
                float w = col[pp] * inv;
                sS[pp * MC + tid] = w;
                ph[pp * PIK + tid] = __float2half(w);
            }
        }
    }
    __syncthreads();

    // ---- Phase 4: new_proto = pi_ @ tok via tensor cores; epilogue from frags --
    // Warp w: n-cols [32w, 32w+32) as 4 n-tiles; A = pi_h, B = tok_h (trans).
    {
        float cc[4][4];
        #pragma unroll
        for (int nt = 0; nt < 4; nt++)
            #pragma unroll
            for (int q = 0; q < 4; q++) cc[nt][q] = 0.f;

        const int g  = lane >> 3;
        const int r8 = lane & 7;
        unsigned a_base = (unsigned)__cvta_generic_to_shared(
            smc + OFFB_PIH + ((g & 1) * 8 + r8) * (PIK * 2) + (g >> 1) * 16);
        const int brow = lane & 15;
        for (int k = 0; k < ks; k++) {
            unsigned a0, a1, a2, a3;
            ldm_x4(a_base + k * 32, a0, a1, a2, a3);
            #pragma unroll
            for (int nt = 0; nt < 4; nt++) {
                unsigned b0, b1;
                unsigned b_addr = (unsigned)__cvta_generic_to_shared(
                    smc + OFFB_TOKH + (k * 16 + brow) * ROWB + (wid * 32 + nt * 8) * 2);
                ldm_x2t(b_addr, b0, b1);
                mma16816(cc[nt][0], cc[nt][1], cc[nt][2], cc[nt][3],
                         a0, a1, a2, a3, b0, b1);
            }
        }

        const int row  = lane >> 2;          // fragment row (0..7); also row+8
        const int tcol = lane & 3;
        const int hi_ok = (row + 8 < NUM_PROTO);

        if (m > TCAP) {  // rare tail: add scalar contributions into fragments
            for (int j = TCAP; j < m; j++) {
                float iv = invn[j];
                float wlo = sS[row * MC + j];
                float whi = hi_ok ? sS[(row + 8) * MC + j] : 0.f;
                const float* tr = tokens + (size_t)idx[j] * EMBED_D;
                #pragma unroll
                for (int nt = 0; nt < 4; nt++) {
                    int n = wid * 32 + nt * 8 + 2 * tcol;
                    float t0 = tr[n] * iv, t1 = tr[n + 1] * iv;
                    cc[nt][0] += wlo * t0; cc[nt][1] += wlo * t1;
                    cc[nt][2] += whi * t0; cc[nt][3] += whi * t1;
                }
            }
        }

        // blend with protos (direct global loads), per-row partial ss
        float2 vlo[4], vhi[4];
        float ss_lo = 0.f, ss_hi = 0.f;
        #pragma unroll
        for (int nt = 0; nt < 4; nt++) {
            int n = wid * 32 + nt * 8 + 2 * tcol;
            float2 plo = *(const float2*)(protos_g + ((size_t)c * NUM_PROTO + row) * EMBED_D + n);
            vlo[nt].x = (1.0f - MOM) * plo.x + MOM * cc[nt][0];
            vlo[nt].y = (1.0f - MOM) * plo.y + MOM * cc[nt][1];
            ss_lo += vlo[nt].x * vlo[nt].x + vlo[nt].y * vlo[nt].y;
            if (hi_ok) {
                float2 phi = *(const float2*)(protos_g + ((size_t)c * NUM_PROTO + row + 8) * EMBED_D + n);
                vhi[nt].x = (1.0f - MOM) * phi.x + MOM * cc[nt][2];
                vhi[nt].y = (1.0f - MOM) * phi.y + MOM * cc[nt][3];
                ss_hi += vhi[nt].x * vhi[nt].x + vhi[nt].y * vhi[nt].y;
            }
        }
        // quad reduce (lanes 4r..4r+3 share a row)
        ss_lo += __shfl_xor_sync(0xffffffffu, ss_lo, 1);
        ss_lo += __shfl_xor_sync(0xffffffffu, ss_lo, 2);
        ss_hi += __shfl_xor_sync(0xffffffffu, ss_hi, 1);
        ss_hi += __shfl_xor_sync(0xffffffffu, ss_hi, 2);
        if (tcol == 0) {
            stage2[row * 16 + wid] = ss_lo;              // transposed: [row][warp]
            if (hi_ok) stage2[(row + 8) * 16 + wid] = ss_hi;
        }
        __syncthreads();
        if (wid == 0 && lane < NUM_PROTO) {              // row sums via 4x LDS.128
            const float4* s4 = (const float4*)(stage2 + lane * 16);
            float4 q0 = s4[0], q1 = s4[1], q2 = s4[2], q3 = s4[3];
            su2[lane] = q0.x+q0.y+q0.z+q0.w + q1.x+q1.y+q1.z+q1.w
                      + q2.x+q2.y+q2.z+q2.w + q3.x+q3.y+q3.z+q3.w;
        }
        __syncthreads();

        float inv_lo = rsqrtf(su2[row]);
        float inv_hi = hi_ok ? rsqrtf(su2[row + 8]) : 0.f;
        #pragma unroll
        for (int nt = 0; nt < 4; nt++) {
            int n = wid * 32 + nt * 8 + 2 * tcol;
            *(float2*)(out + ((size_t)(c * NUM_PROTO + row)) * EMBED_D + n)
                = make_float2(vlo[nt].x * inv_lo, vlo[nt].y * inv_lo);
            if (hi_ok)
                *(float2*)(out + ((size_t)(c * NUM_PROTO + row + 8)) * EMBED_D + n)
                    = make_float2(vhi[nt].x * inv_hi, vhi[nt].y * inv_hi);
        }
    }
}

// ---------------------------------------------------------------------------
extern "C" void kernel_launch(void* const* d_in, const int* in_sizes, int n_in,
                              void* d_out, int out_size) {
    const float* tokens = (const float*)d_in[0];
    const void*  labels = d_in[1];
    const float* protos = (const float*)d_in[2];
    float* out = (float*)d_out;

    cudaFuncSetAttribute(fused_kernel,
                         cudaFuncAttributeMaxDynamicSharedMemorySize, SMEM_BYTES);
    fused_kernel<<<NUM_CLASSES, NT, SMEM_BYTES>>>(tokens, labels, protos, out);
}

// round 16
// speedup vs baseline: 1.0035x; 1.0035x over previous
#include <cuda_runtime.h>
#include <cuda_fp16.h>
#include <math.h>

#define NUM_CLASSES 200
#define NUM_PROTO   10
#define EMBED_D     512
#define NQ          8192
#define MC          96      // S/sv/idx capacity
#define TCAP        64      // fp16 rows staged in smem
#define EPSILON_    0.01f
#define ITERS       5
#define MOM         0.02f
#define NT          512
#define ROWB        1040    // bytes per staged fp16 row (520 halves, bank-staggered)
#define PIK         104     // pi_h K padding (208B row stride: conflict-free ldmatrix)

// dynamic smem layout (bytes), all 16B aligned
#define OFFB_TOKH   0                       // 64 * 1040 = 66560
#define OFFB_PROTOH 66560                   // 16 * 1040 = 16640
#define OFFB_S      83200                   // 10*96*4 = 3840
#define OFFB_SV     87040                   // 96*4
#define OFFB_INVN   87424                   // 96*4
#define OFFB_IDX    87808                   // 96*4
#define OFFB_PIH    88192                   // 16 * 208 = 3328 fp16 pi
#define SMEM_BYTES  91520

extern __shared__ char smc[];

__device__ __forceinline__ void ldm_x4(unsigned addr, unsigned &a0, unsigned &a1,
                                       unsigned &a2, unsigned &a3) {
    asm volatile("ldmatrix.sync.aligned.m8n8.x4.shared.b16 {%0,%1,%2,%3}, [%4];"
        : "=r"(a0), "=r"(a1), "=r"(a2), "=r"(a3) : "r"(addr));
}
__device__ __forceinline__ void ldm_x2(unsigned addr, unsigned &b0, unsigned &b1) {
    asm volatile("ldmatrix.sync.aligned.m8n8.x2.shared.b16 {%0,%1}, [%2];"
        : "=r"(b0), "=r"(b1) : "r"(addr));
}
__device__ __forceinline__ void ldm_x2t(unsigned addr, unsigned &b0, unsigned &b1) {
    asm volatile("ldmatrix.sync.aligned.m8n8.x2.trans.shared.b16 {%0,%1}, [%2];"
        : "=r"(b0), "=r"(b1) : "r"(addr));
}
__device__ __forceinline__ void mma16816(float &c0, float &c1, float &c2, float &c3,
                                         unsigned a0, unsigned a1, unsigned a2, unsigned a3,
                                         unsigned b0, unsigned b1) {
    asm volatile("mma.sync.aligned.m16n8k16.row.col.f32.f16.f16.f32 "
        "{%0,%1,%2,%3},{%4,%5,%6,%7},{%8,%9},{%0,%1,%2,%3};"
        : "+f"(c0), "+f"(c1), "+f"(c2), "+f"(c3)
        : "r"(a0), "r"(a1), "r"(a2), "r"(a3), "r"(b0), "r"(b1));
}

__global__ void __launch_bounds__(NT, 2) fused_kernel(
    const float* __restrict__ tokens,
    const void*  __restrict__ labels_v,
    const float* __restrict__ protos_g,
    float* __restrict__ out)
{
    __shared__ float su[NUM_PROTO];
    __shared__ __align__(16) float stage2[256];   // [16 rows][16 warps] partial ss
    __shared__ float su2[16];
    __shared__ int   s_cnt;

    float* sS   = (float*)(smc + OFFB_S);
    float* sv   = (float*)(smc + OFFB_SV);
    float* invn = (float*)(smc + OFFB_INVN);
    int*   idx  = (int*)(smc + OFFB_IDX);

    const int c    = blockIdx.x;
    const int tid  = threadIdx.x;
    const int lane = tid & 31;
    const int wid  = tid >> 5;

    if (tid == 0) s_cnt = 0;
    if (tid < NUM_PROTO) su[tid] = 0.f;
    if (tid < MC)        sv[tid] = 0.f;
    // zero pi_h (rows 10-15 and cols >= m must be 0 for the phase-4 MMA)
    for (int t = tid; t < 16 * PIK / 2; t += NT)
        ((unsigned*)(smc + OFFB_PIH))[t] = 0u;

    // ---- label scan round 1 + dtype detect, one L2 exposure ----
    // First 32KB: int64 buffer -> labels 0..4095 (odd words all zero);
    // int32 buffer -> ALL labels (odd words nonzero somewhere).
    const int4* L = (const int4*)labels_v;
    int4 v[4];
    #pragma unroll
    for (int k = 0; k < 4; k++) v[k] = L[tid + NT * k];
    int nz = v[0].y | v[0].w | v[1].y | v[1].w |
             v[2].y | v[2].w | v[3].y | v[3].w;
    const int is64 = __syncthreads_or(nz != 0) ? 0 : 1;  // barrier orders inits

    if (!is64) {
        #pragma unroll
        for (int k = 0; k < 4; k++) {
            int base = 4 * (tid + NT * k);
            if (v[k].x == c) { int p = atomicAdd(&s_cnt, 1); if (p < MC) idx[p] = base; }
            if (v[k].y == c) { int p = atomicAdd(&s_cnt, 1); if (p < MC) idx[p] = base + 1; }
            if (v[k].z == c) { int p = atomicAdd(&s_cnt, 1); if (p < MC) idx[p] = base + 2; }
            if (v[k].w == c) { int p = atomicAdd(&s_cnt, 1); if (p < MC) idx[p] = base + 3; }
        }
    } else {
        int4 w4[4];
        #pragma unroll
        for (int k = 0; k < 4; k++) w4[k] = L[tid + NT * (k + 4)];
        #pragma unroll
        for (int k = 0; k < 4; k++) {
            int base = 2 * (tid + NT * k);
            if (v[k].x == c) { int p = atomicAdd(&s_cnt, 1); if (p < MC) idx[p] = base; }
            if (v[k].z == c) { int p = atomicAdd(&s_cnt, 1); if (p < MC) idx[p] = base + 1; }
        }
        #pragma unroll
        for (int k = 0; k < 4; k++) {
            int base = 2 * (tid + NT * (k + 4));
            if (w4[k].x == c) { int p = atomicAdd(&s_cnt, 1); if (p < MC) idx[p] = base; }
            if (w4[k].z == c) { int p = atomicAdd(&s_cnt, 1); if (p < MC) idx[p] = base + 1; }
        }
    }

    // ---- proto fp32 -> fp16 smem (overlaps label extraction latency) ----
    {
        const float4* pg = (const float4*)(protos_g + (size_t)c * NUM_PROTO * EMBED_D);
        for (int t = tid; t < NUM_PROTO * EMBED_D / 4; t += NT) {
            float4 vv = pg[t];
            int p = t >> 7, d4 = t & 127;
            __half2* dst = (__half2*)(smc + OFFB_PROTOH + p * ROWB) + d4 * 2;
            dst[0] = __floats2half2_rn(vv.x, vv.y);
            dst[1] = __floats2half2_rn(vv.z, vv.w);
        }
    }
    __syncthreads();
    const int m    = (s_cnt < MC) ? s_cnt : MC;
    const int mcap = (m < TCAP) ? m : TCAP;
    const int ks   = (mcap + 15) >> 4;          // phase-4 k-steps

    // ---- Pre-pass: warp per row: load fp32, normalize, stage fp16 ----
    for (int j = wid; j < m; j += 16) {
        const float4* tk = (const float4*)(tokens + (size_t)idx[j] * EMBED_D);
        float4 r[4];
        float ss = 0.f;
        #pragma unroll
        for (int k = 0; k < 4; k++) {
            r[k] = tk[lane + 32 * k];
            ss += r[k].x*r[k].x + r[k].y*r[k].y + r[k].z*r[k].z + r[k].w*r[k].w;
        }
        #pragma unroll
        for (int o = 16; o; o >>= 1) ss += __shfl_xor_sync(0xffffffffu, ss, o);
        float inv = rsqrtf(ss);
        if (lane == 0) invn[j] = inv;
        if (j < TCAP) {
            __half2* row = (__half2*)(smc + OFFB_TOKH + j * ROWB);
            #pragma unroll
            for (int k = 0; k < 4; k++) {
                int h2 = (lane + 32 * k) * 2;
                row[h2]     = __floats2half2_rn(r[k].x * inv, r[k].y * inv);
                row[h2 + 1] = __floats2half2_rn(r[k].z * inv, r[k].w * inv);
            }
        }
    }
    // zero tok_h rows [mcap, 16*ks) — read by phase-4 MMA, never staged
    for (int t = tid; t < (16 * ks - mcap) * 260; t += NT) {
        int r = mcap + t / 260, q = t % 260;
        *((unsigned*)(smc + OFFB_TOKH + r * ROWB) + q) = 0u;
    }
    __syncthreads();

    // ---- Phase 2: S = proto @ tok_norm^T via tensor cores ----
    if (wid < 8) {
        const int jt = wid * 8;
        const int g  = lane >> 3;
        const int r8 = lane & 7;
        unsigned a_base = (unsigned)__cvta_generic_to_shared(
            smc + OFFB_PROTOH + ((g & 1) * 8 + r8) * ROWB + (g >> 1) * 16);
        unsigned b_base = (unsigned)__cvta_generic_to_shared(
            smc + OFFB_TOKH + (jt + r8) * ROWB + (g & 1) * 16);
        float c0 = 0.f, c1 = 0.f, c2 = 0.f, c3 = 0.f;
        #pragma unroll 8
        for (int kk = 0; kk < 32; kk++) {
            unsigned a0, a1, a2, a3, b0, b1;
            ldm_x4(a_base + kk * 32, a0, a1, a2, a3);
            ldm_x2(b_base + kk * 32, b0, b1);
            mma16816(c0, c1, c2, c3, a0, a1, a2, a3, b0, b1);
        }
        const int row = lane >> 2;
        const int j0  = jt + 2 * (lane & 3);
        sS[row * MC + j0]     = c0;
        sS[row * MC + j0 + 1] = c1;
        if (row + 8 < NUM_PROTO) {
            sS[(row + 8) * MC + j0]     = c2;
            sS[(row + 8) * MC + j0 + 1] = c3;
        }
    } else if (m > TCAP) {
        // rare fallback: rows 64..m-1 from raw fp32 global -> needs invn
        for (int j = TCAP + (wid - 8); j < m; j += 8) {
            const float4* tk = (const float4*)(tokens + (size_t)idx[j] * EMBED_D + 16 * lane);
            float4 t[4];
            #pragma unroll
            for (int k = 0; k < 4; k++) t[k] = tk[k];
            float iv = invn[j];
            #pragma unroll
            for (int p = 0; p < NUM_PROTO; p++) {
                const __half2* ph = (const __half2*)(smc + OFFB_PROTOH + p * ROWB) + lane * 8;
                float d = 0.f;
                #pragma unroll
                for (int k = 0; k < 4; k++) {
                    float2 f0 = __half22float2(ph[2 * k]);
                    float2 f1 = __half22float2(ph[2 * k + 1]);
                    d += f0.x * t[k].x + f0.y * t[k].y + f1.x * t[k].z + f1.y * t[k].w;
                }
                #pragma unroll
                for (int o = 16; o; o >>= 1) d += __shfl_xor_sync(0xffffffffu, d, o);
                if (lane == 0) sS[p * MC + j] = d * iv;
            }
        }
    }
    __syncthreads();

    // ---- Phase 3: Sinkhorn (warps 0-9; named barrier 1, 320 threads) ----
    if (m > 0 && wid < NUM_PROTO) {
        const float log_a = __logf(1.0f / (float)NUM_PROTO + 1e-8f);
        const float log_b = __logf(1.0f / (float)m + 1e-8f);
        const float inv_eps = 1.0f / EPSILON_;
        const int p = wid;

        const float s0 = (lane      < m) ? sS[p * MC + lane]      : -INFINITY;
        const float s1 = (lane + 32 < m) ? sS[p * MC + lane + 32] : -INFINITY;
        const float s2 = (lane + 64 < m) ? sS[p * MC + lane + 64] : -INFINITY;
        float scol[NUM_PROTO];
        if (tid < m) {
            #pragma unroll
            for (int pp = 0; pp < NUM_PROTO; pp++) scol[pp] = sS[pp * MC + tid];
        }

        for (int it = 0; it < ITERS; it++) {
            {
                float up = su[p];
                float t0 = (s0 + up + sv[lane])      * inv_eps;
                float t1 = (s1 + up + sv[lane + 32]) * inv_eps;
                float t2 = (s2 + up + sv[lane + 64]) * inv_eps;
                float mx = fmaxf(t0, fmaxf(t1, t2));
                #pragma unroll
                for (int o = 16; o; o >>= 1)
                    mx = fmaxf(mx, __shfl_xor_sync(0xffffffffu, mx, o));
                float sum = __expf(t0 - mx) + __expf(t1 - mx) + __expf(t2 - mx);
                #pragma unroll
                for (int o = 16; o; o >>= 1)
                    sum += __shfl_xor_sync(0xffffffffu, sum, o);
                if (lane == 0)
                    su[p] = EPSILON_ * (log_a - (mx + __logf(sum))) + up;
            }
            asm volatile("bar.sync 1, 320;" ::: "memory");
            if (tid < m) {
                float vj = sv[tid];
                float mx = -INFINITY;
                #pragma unroll
                for (int pp = 0; pp < NUM_PROTO; pp++)
                    mx = fmaxf(mx, (scol[pp] + su[pp] + vj) * inv_eps);
                float sum = 0.f;
                #pragma unroll
                for (int pp = 0; pp < NUM_PROTO; pp++)
                    sum += __expf((scol[pp] + su[pp] + vj) * inv_eps - mx);
                sv[tid] = EPSILON_ * (log_b - (mx + __logf(sum))) + vj;
            }
            asm volatile("bar.sync 1, 320;" ::: "memory");
        }

        if (tid < m) {   // pi, column-normalized; fp32 to sS (tail) + fp16 to pi_h (MMA)
            float vj = sv[tid];
            float col[NUM_PROTO];
            float cs = 0.f;
            #pragma unroll
            for (int pp = 0; pp < NUM_PROTO; pp++) {
                col[pp] = __expf((scol[pp] + su[pp] + vj) * inv_eps);
                cs += col[pp];
            }
            float inv = 1.0f / cs;
            __half* ph = (__half*)(smc + OFFB_PIH);
            #pragma unroll
            for (int pp = 0; pp < NUM_PROTO; pp++) {
                float w = col[pp] * inv;
                sS[pp * MC + tid] = w;
                ph[pp * PIK + tid] = __float2half(w);
            }
        }
    }
    __syncthreads();

    // ---- Phase 4: new_proto = pi_ @ tok via tensor cores; epilogue from frags --
    // Warp w: n-cols [32w, 32w+32) as 4 n-tiles; A = pi_h, B = tok_h (trans).
    {
        float cc[4][4];
        #pragma unroll
        for (int nt = 0; nt < 4; nt++)
            #pragma unroll
            for (int q = 0; q < 4; q++) cc[nt][q] = 0.f;

        const int g  = lane >> 3;
        const int r8 = lane & 7;
        unsigned a_base = (unsigned)__cvta_generic_to_shared(
            smc + OFFB_PIH + ((g & 1) * 8 + r8) * (PIK * 2) + (g >> 1) * 16);
        const int brow = lane & 15;
        for (int k = 0; k < ks; k++) {
            unsigned a0, a1, a2, a3;
            ldm_x4(a_base + k * 32, a0, a1, a2, a3);
            #pragma unroll
            for (int nt = 0; nt < 4; nt++) {
                unsigned b0, b1;
                unsigned b_addr = (unsigned)__cvta_generic_to_shared(
                    smc + OFFB_TOKH + (k * 16 + brow) * ROWB + (wid * 32 + nt * 8) * 2);
                ldm_x2t(b_addr, b0, b1);
                mma16816(cc[nt][0], cc[nt][1], cc[nt][2], cc[nt][3],
                         a0, a1, a2, a3, b0, b1);
            }
        }

        const int row  = lane >> 2;          // fragment row (0..7); also row+8
        const int tcol = lane & 3;
        const int hi_ok = (row + 8 < NUM_PROTO);

        if (m > TCAP) {  // rare tail: add scalar contributions into fragments
            for (int j = TCAP; j < m; j++) {
                float iv = invn[j];
                float wlo = sS[row * MC + j];
                float whi = hi_ok ? sS[(row + 8) * MC + j] : 0.f;
                const float* tr = tokens + (size_t)idx[j] * EMBED_D;
                #pragma unroll
                for (int nt = 0; nt < 4; nt++) {
                    int n = wid * 32 + nt * 8 + 2 * tcol;
                    float t0 = tr[n] * iv, t1 = tr[n + 1] * iv;
                    cc[nt][0] += wlo * t0; cc[nt][1] += wlo * t1;
                    cc[nt][2] += whi * t0; cc[nt][3] += whi * t1;
                }
            }
        }

        // blend with protos (direct global loads), per-row partial ss
        float2 vlo[4], vhi[4];
        float ss_lo = 0.f, ss_hi = 0.f;
        #pragma unroll
        for (int nt = 0; nt < 4; nt++) {
            int n = wid * 32 + nt * 8 + 2 * tcol;
            float2 plo = *(const float2*)(protos_g + ((size_t)c * NUM_PROTO + row) * EMBED_D + n);
            vlo[nt].x = (1.0f - MOM) * plo.x + MOM * cc[nt][0];
            vlo[nt].y = (1.0f - MOM) * plo.y + MOM * cc[nt][1];
            ss_lo += vlo[nt].x * vlo[nt].x + vlo[nt].y * vlo[nt].y;
            if (hi_ok) {
                float2 phi = *(const float2*)(protos_g + ((size_t)c * NUM_PROTO + row + 8) * EMBED_D + n);
                vhi[nt].x = (1.0f - MOM) * phi.x + MOM * cc[nt][2];
                vhi[nt].y = (1.0f - MOM) * phi.y + MOM * cc[nt][3];
                ss_hi += vhi[nt].x * vhi[nt].x + vhi[nt].y * vhi[nt].y;
            }
        }
        // quad reduce (lanes 4r..4r+3 share a row)
        ss_lo += __shfl_xor_sync(0xffffffffu, ss_lo, 1);
        ss_lo += __shfl_xor_sync(0xffffffffu, ss_lo, 2);
        ss_hi += __shfl_xor_sync(0xffffffffu, ss_hi, 1);
        ss_hi += __shfl_xor_sync(0xffffffffu, ss_hi, 2);
        if (tcol == 0) {
            stage2[row * 16 + wid] = ss_lo;              // transposed: [row][warp]
            if (hi_ok) stage2[(row + 8) * 16 + wid] = ss_hi;
        }
        __syncthreads();
        if (wid == 0 && lane < NUM_PROTO) {              // row sums via 4x LDS.128
            const float4* s4 = (const float4*)(stage2 + lane * 16);
            float4 q0 = s4[0], q1 = s4[1], q2 = s4[2], q3 = s4[3];
            su2[lane] = q0.x+q0.y+q0.z+q0.w + q1.x+q1.y+q1.z+q1.w
                      + q2.x+q2.y+q2.z+q2.w + q3.x+q3.y+q3.z+q3.w;
        }
        __syncthreads();

        float inv_lo = rsqrtf(su2[row]);
        float inv_hi = hi_ok ? rsqrtf(su2[row + 8]) : 0.f;
        #pragma unroll
        for (int nt = 0; nt < 4; nt++) {
            int n = wid * 32 + nt * 8 + 2 * tcol;
            *(float2*)(out + ((size_t)(c * NUM_PROTO + row)) * EMBED_D + n)
                = make_float2(vlo[nt].x * inv_lo, vlo[nt].y * inv_lo);
            if (hi_ok)
                *(float2*)(out + ((size_t)(c * NUM_PROTO + row + 8)) * EMBED_D + n)
                    = make_float2(vhi[nt].x * inv_hi, vhi[nt].y * inv_hi);
        }
    }
}

// ---------------------------------------------------------------------------
extern "C" void kernel_launch(void* const* d_in, const int* in_sizes, int n_in,
                              void* d_out, int out_size) {
    const float* tokens = (const float*)d_in[0];
    const void*  labels = d_in[1];
    const float* protos = (const float*)d_in[2];
    float* out = (float*)d_out;

    cudaFuncSetAttribute(fused_kernel,
                         cudaFuncAttributeMaxDynamicSharedMemorySize, SMEM_BYTES);
    fused_kernel<<<NUM_CLASSES, NT, SMEM_BYTES>>>(tokens, labels, protos, out);
}